// round 5
// baseline (speedup 1.0000x reference)
#include <cuda_runtime.h>
#include <cstdint>

#define BB   8
#define CC   256
#define NN   16384

// Scratch (device-global; no allocations allowed)
__device__ float g_K[(size_t)BB * 256 * NN];  // exp(K + bk), tf32-rounded
__device__ float g_V[(size_t)BB * 256 * NN];  // V + bv, tf32-rounded
__device__ float g_s[BB * 256];               // softmax denominators

// ---------------------------------------------------------------------------
// tf32 helpers (mma.sync path: works on plain sm_103 virtual arch)
// ---------------------------------------------------------------------------
__device__ __forceinline__ float to_tf32(float x) {
    uint32_t u;
    asm("cvt.rna.tf32.f32 %0, %1;" : "=r"(u) : "f"(x));
    return __uint_as_float(u);
}

__device__ __forceinline__ void mma_tf32(float* d, const uint32_t* a,
                                         const uint32_t* b) {
    asm volatile(
        "mma.sync.aligned.m16n8k8.row.col.f32.tf32.tf32.f32 "
        "{%0,%1,%2,%3}, {%4,%5,%6,%7}, {%8,%9}, {%0,%1,%2,%3};"
        : "+f"(d[0]), "+f"(d[1]), "+f"(d[2]), "+f"(d[3])
        : "r"(a[0]), "r"(a[1]), "r"(a[2]), "r"(a[3]), "r"(b[0]), "r"(b[1]));
}

// Warp-tile 32x32 MMA over one smem chunk. NKS k-steps of 8.
template <int NKS, int SMSV>
__device__ __forceinline__ void warp_mma(const float* sA, const float* sB,
                                         int wm, int wn, int lr, int lc,
                                         float acc[2][4][4]) {
    #pragma unroll
    for (int ks = 0; ks < NKS; ++ks) {
        const int kc = ks * 8;
        uint32_t a[2][4], bf[4][2];
        #pragma unroll
        for (int i = 0; i < 2; ++i) {
            const float* p0 = &sA[(wm + i * 16 + lr) * SMSV + kc + lc];
            const float* p1 = p0 + 8 * SMSV;
            a[i][0] = __float_as_uint(p0[0]);
            a[i][1] = __float_as_uint(p1[0]);
            a[i][2] = __float_as_uint(p0[4]);
            a[i][3] = __float_as_uint(p1[4]);
        }
        #pragma unroll
        for (int j = 0; j < 4; ++j) {
            const float* p = &sB[(wn + j * 8 + lr) * SMSV + kc + lc];
            bf[j][0] = __float_as_uint(p[0]);
            bf[j][1] = __float_as_uint(p[4]);
        }
        #pragma unroll
        for (int i = 0; i < 2; ++i)
            #pragma unroll
            for (int j = 0; j < 4; ++j) mma_tf32(acc[i][j], a[i], bf[j]);
    }
}

// ---------------------------------------------------------------------------
// K0: zero output and g_s
// ---------------------------------------------------------------------------
__global__ void k0_zero(float* __restrict__ out, int n) {
    int i = blockIdx.x * 256 + threadIdx.x;
    if (i < n) out[i] = 0.0f;
    if (i < BB * 256) g_s[i] = 0.0f;
}

// ---------------------------------------------------------------------------
// K1: (K|V) = W @ x + bias; K-tiles get exp + rowsum fused into epilogue.
// 512 thr, CTA tile 128x128, contraction chunk 64 (4 iters), 2-stage smem
// double buffer with register prefetch. grid (4 m-tiles, 128 n-tiles, 8 b).
// ---------------------------------------------------------------------------
#define SMS1      68
#define K1_STAGE  (128 * SMS1 * 2)          // floats (A tile + B tile)
#define K1_SMEM   (2 * K1_STAGE * 4)        // bytes

__device__ __forceinline__ void k1_load(const float* Wrow0, const float* Xg,
                                        int c0, int tid, float4* aT, float* bT) {
    #pragma unroll
    for (int r = 0; r < 4; ++r) {
        const int idx2 = tid + r * 512;
        const int row = idx2 >> 4, q = (idx2 & 15) * 4;
        aT[r] = *(const float4*)(Wrow0 + (size_t)row * CC + c0 + q);
    }
    const float* p = Xg + (size_t)c0 * NN;
    const int lane = tid & 31;
    #pragma unroll
    for (int i2 = 0; i2 < 4; ++i2) {
        const int nl = i2 * 32 + lane;
        bT[i2 * 4 + 0] = p[nl];
        bT[i2 * 4 + 1] = p[(size_t)NN + nl];
        bT[i2 * 4 + 2] = p[2 * (size_t)NN + nl];
        bT[i2 * 4 + 3] = p[3 * (size_t)NN + nl];
    }
}

__device__ __forceinline__ void k1_store(float* sA, float* sB, int tid, int wid,
                                         const float4* aT, const float* bT) {
    #pragma unroll
    for (int r = 0; r < 4; ++r) {
        const int idx2 = tid + r * 512;
        const int row = idx2 >> 4, q = (idx2 & 15) * 4;
        float* d = &sA[row * SMS1 + q];
        d[0] = to_tf32(aT[r].x); d[1] = to_tf32(aT[r].y);
        d[2] = to_tf32(aT[r].z); d[3] = to_tf32(aT[r].w);
    }
    const int lane = tid & 31;
    #pragma unroll
    for (int i2 = 0; i2 < 4; ++i2) {
        const int nl = i2 * 32 + lane;
        float* d = &sB[nl * SMS1 + 4 * wid];
        d[0] = to_tf32(bT[i2 * 4 + 0]); d[1] = to_tf32(bT[i2 * 4 + 1]);
        d[2] = to_tf32(bT[i2 * 4 + 2]); d[3] = to_tf32(bT[i2 * 4 + 3]);
    }
}

__global__ void __launch_bounds__(512, 1)
k1_gemm(const float* __restrict__ x,
        const float* __restrict__ Wk, const float* __restrict__ bk,
        const float* __restrict__ Wv, const float* __restrict__ bv) {
    extern __shared__ float sm1[];
    const int tid  = threadIdx.x;
    const int wid  = tid >> 5;
    const int lane = tid & 31;
    const int lr   = lane >> 2, lc = lane & 3;
    const int wm   = (wid & 3) * 32;
    const int wn   = (wid >> 2) * 32;

    const int mtile = blockIdx.x;
    const int n0    = blockIdx.y * 128;
    const int b     = blockIdx.z;
    const bool isK  = (mtile < 2);
    const int mrow0 = (mtile & 1) * 128;

    const float* Wrow0 = (isK ? Wk : Wv) + (size_t)mrow0 * CC;
    const float* bias  = isK ? bk : bv;
    const float* Xg = x + (size_t)b * CC * NN + n0 + (size_t)(4 * wid) * NN;

    float acc[2][4][4];
    #pragma unroll
    for (int i = 0; i < 2; ++i)
        #pragma unroll
        for (int j = 0; j < 4; ++j)
            #pragma unroll
            for (int t = 0; t < 4; ++t) acc[i][j][t] = 0.0f;

    float4 aT[4];
    float  bT[16];

    k1_load(Wrow0, Xg, 0, tid, aT, bT);
    k1_store(sm1, sm1 + 128 * SMS1, tid, wid, aT, bT);
    __syncthreads();

    for (int ic = 0; ic < 4; ++ic) {
        if (ic < 3) k1_load(Wrow0, Xg, (ic + 1) * 64, tid, aT, bT);
        const float* sA = sm1 + (ic & 1) * K1_STAGE;
        warp_mma<8, SMS1>(sA, sA + 128 * SMS1, wm, wn, lr, lc, acc);
        if (ic < 3) {
            float* dA = sm1 + ((ic + 1) & 1) * K1_STAGE;
            k1_store(dA, dA + 128 * SMS1, tid, wid, aT, bT);
        }
        __syncthreads();
    }

    // Epilogue: bias, (exp + rowsum for K), tf32-round, store.
    float* gout = isK ? g_K : g_V;
    float rs[2][2] = {{0.f, 0.f}, {0.f, 0.f}};
    #pragma unroll
    for (int i = 0; i < 2; ++i) {
        const int ch0 = mrow0 + wm + i * 16 + lr;
        const int ch1 = ch0 + 8;
        const float b0 = bias[ch0], b1 = bias[ch1];
        float* r0 = gout + ((size_t)b * 256 + ch0) * NN + n0 + wn + 2 * lc;
        float* r1 = gout + ((size_t)b * 256 + ch1) * NN + n0 + wn + 2 * lc;
        #pragma unroll
        for (int j = 0; j < 4; ++j) {
            float v0 = acc[i][j][0] + b0, v1 = acc[i][j][1] + b0;
            float v2 = acc[i][j][2] + b1, v3 = acc[i][j][3] + b1;
            if (isK) {
                v0 = to_tf32(__expf(v0)); v1 = to_tf32(__expf(v1));
                v2 = to_tf32(__expf(v2)); v3 = to_tf32(__expf(v3));
                rs[i][0] += v0 + v1;
                rs[i][1] += v2 + v3;
            } else {
                v0 = to_tf32(v0); v1 = to_tf32(v1);
                v2 = to_tf32(v2); v3 = to_tf32(v3);
            }
            *(float2*)(r0 + j * 8) = make_float2(v0, v1);
            *(float2*)(r1 + j * 8) = make_float2(v2, v3);
        }
    }
    if (isK) {
        #pragma unroll
        for (int i = 0; i < 2; ++i)
            #pragma unroll
            for (int h = 0; h < 2; ++h) {
                float v = rs[i][h];
                v += __shfl_xor_sync(0xffffffffu, v, 1);
                v += __shfl_xor_sync(0xffffffffu, v, 2);
                if (lc == 0) {
                    int ch = mrow0 + wm + i * 16 + lr + h * 8;
                    atomicAdd(&g_s[b * 256 + ch], v);
                }
            }
    }
}

// ---------------------------------------------------------------------------
// K3: context = (1/s) * expK @ V^T. Inputs are pre-rounded tf32 -> cp.async
// double-buffered loads, no cvt. 512 thr, warp tile 32x32, chunk 32,
// contraction split 8 ways (2048 each = 64 chunks). atomicAdd epilogue.
// ---------------------------------------------------------------------------
#define SMS3      36
#define K3_STAGE  (128 * SMS3 * 2)          // floats
#define K3_SMEM   (2 * K3_STAGE * 4)        // bytes

__device__ __forceinline__ void k3_prefetch(uint32_t smbase, int st,
                                            const float* Kb, const float* Vb,
                                            int c0, int tid) {
    const uint32_t sA = smbase + (uint32_t)(st * K3_STAGE * 4);
    const uint32_t sB = sA + 128 * SMS3 * 4;
    #pragma unroll
    for (int r = 0; r < 2; ++r) {
        const int idx2 = tid + r * 512;
        const int row = idx2 >> 3, q = (idx2 & 7) * 4;
        const uint32_t off = (uint32_t)(row * SMS3 + q) * 4;
        const float* srcA = Kb + (size_t)row * NN + c0 + q;
        const float* srcB = Vb + (size_t)row * NN + c0 + q;
        asm volatile("cp.async.cg.shared.global [%0], [%1], 16;"
                     :: "r"(sA + off), "l"(srcA) : "memory");
        asm volatile("cp.async.cg.shared.global [%0], [%1], 16;"
                     :: "r"(sB + off), "l"(srcB) : "memory");
    }
}

__global__ void __launch_bounds__(512, 1)
k3_context(float* __restrict__ out) {
    extern __shared__ float sm3[];
    const int tid  = threadIdx.x;
    const int wid  = tid >> 5;
    const int lane = tid & 31;
    const int lr   = lane >> 2, lc = lane & 3;
    const int wm   = (wid & 3) * 32;
    const int wn   = (wid >> 2) * 32;

    const int km0 = (blockIdx.x & 1) * 128;
    const int vm0 = (blockIdx.x >> 1) * 128;
    const int nb  = blockIdx.y * 2048;
    const int b   = blockIdx.z;

    const float* Kbase = g_K + ((size_t)b * 256 + km0) * NN + nb;
    const float* Vbase = g_V + ((size_t)b * 256 + vm0) * NN + nb;
    const uint32_t smbase = (uint32_t)__cvta_generic_to_shared(sm3);

    float acc[2][4][4];
    #pragma unroll
    for (int i = 0; i < 2; ++i)
        #pragma unroll
        for (int j = 0; j < 4; ++j)
            #pragma unroll
            for (int t = 0; t < 4; ++t) acc[i][j][t] = 0.0f;

    k3_prefetch(smbase, 0, Kbase, Vbase, 0, tid);
    asm volatile("cp.async.commit_group;" ::: "memory");
    k3_prefetch(smbase, 1, Kbase, Vbase, 32, tid);
    asm volatile("cp.async.commit_group;" ::: "memory");

    for (int ic = 0; ic < 64; ++ic) {
        asm volatile("cp.async.wait_group 1;" ::: "memory");
        __syncthreads();
        const float* sA = sm3 + (ic & 1) * K3_STAGE;
        warp_mma<4, SMS3>(sA, sA + 128 * SMS3, wm, wn, lr, lc, acc);
        __syncthreads();
        if (ic + 2 < 64)
            k3_prefetch(smbase, ic & 1, Kbase, Vbase, (ic + 2) * 32, tid);
        asm volatile("cp.async.commit_group;" ::: "memory");
    }

    #pragma unroll
    for (int i = 0; i < 2; ++i) {
        const int k0r = km0 + wm + i * 16 + lr;
        const int k1r = k0r + 8;
        const float inv0 = 1.0f / g_s[b * 256 + k0r];
        const float inv1 = 1.0f / g_s[b * 256 + k1r];
        float* r0 = out + ((size_t)b * 256 + k0r) * 256 + vm0 + wn + 2 * lc;
        float* r1 = out + ((size_t)b * 256 + k1r) * 256 + vm0 + wn + 2 * lc;
        #pragma unroll
        for (int j = 0; j < 4; ++j) {
            atomicAdd(r0 + j * 8,     acc[i][j][0] * inv0);
            atomicAdd(r0 + j * 8 + 1, acc[i][j][1] * inv0);
            atomicAdd(r1 + j * 8,     acc[i][j][2] * inv1);
            atomicAdd(r1 + j * 8 + 1, acc[i][j][3] * inv1);
        }
    }
}

// ---------------------------------------------------------------------------
// Launch
// ---------------------------------------------------------------------------
extern "C" void kernel_launch(void* const* d_in, const int* in_sizes, int n_in,
                              void* d_out, int out_size) {
    const float* x  = (const float*)d_in[0];
    const float* Wk = (const float*)d_in[1];
    const float* bk = (const float*)d_in[2];
    const float* Wv = (const float*)d_in[3];
    const float* bv = (const float*)d_in[4];
    float* out = (float*)d_out;

    cudaFuncSetAttribute(k1_gemm, cudaFuncAttributeMaxDynamicSharedMemorySize,
                         K1_SMEM);
    cudaFuncSetAttribute(k3_context, cudaFuncAttributeMaxDynamicSharedMemorySize,
                         K3_SMEM);

    k0_zero<<<(out_size + 255) / 256, 256>>>(out, out_size);

    dim3 g1(4, 128, BB);
    k1_gemm<<<g1, 512, K1_SMEM>>>(x, Wk, bk, Wv, bv);

    dim3 g3(4, 8, BB);
    k3_context<<<g3, 512, K3_SMEM>>>(out);
}

// round 6
// speedup vs baseline: 1.2478x; 1.2478x over previous
#include <cuda_runtime.h>
#include <cstdint>

#define BB   8
#define CC   256
#define NN   16384

// Scratch (device-global; no allocations allowed)
__device__ float g_K[(size_t)BB * 256 * NN];  // exp(K + bk), tf32-rounded
__device__ float g_V[(size_t)BB * 256 * NN];  // V + bv, tf32-rounded
__device__ float g_s[BB * 256];               // softmax denominators
__device__ float g_Wt[512 * 256];             // [Wk; Wv] pre-rounded to tf32

// ---------------------------------------------------------------------------
// tf32 helpers (mma.sync path: works on plain sm_103 virtual arch)
// ---------------------------------------------------------------------------
__device__ __forceinline__ float to_tf32(float x) {
    uint32_t u;
    asm("cvt.rna.tf32.f32 %0, %1;" : "=r"(u) : "f"(x));
    return __uint_as_float(u);
}
__device__ __forceinline__ uint32_t tf32_bits(float x) {
    uint32_t u;
    asm("cvt.rna.tf32.f32 %0, %1;" : "=r"(u) : "f"(x));
    return u;
}

__device__ __forceinline__ void mma_tf32(float* d, const uint32_t* a,
                                         const uint32_t* b) {
    asm volatile(
        "mma.sync.aligned.m16n8k8.row.col.f32.tf32.tf32.f32 "
        "{%0,%1,%2,%3}, {%4,%5,%6,%7}, {%8,%9}, {%0,%1,%2,%3};"
        : "+f"(d[0]), "+f"(d[1]), "+f"(d[2]), "+f"(d[3])
        : "r"(a[0]), "r"(a[1]), "r"(a[2]), "r"(a[3]), "r"(b[0]), "r"(b[1]));
}

#define CPA16(dst, src) \
    asm volatile("cp.async.cg.shared.global [%0], [%1], 16;" \
                 :: "r"(dst), "l"(src) : "memory")
#define CPA_COMMIT() asm volatile("cp.async.commit_group;" ::: "memory")
#define CPA_WAIT1()  asm volatile("cp.async.wait_group 1;" ::: "memory")

// ---------------------------------------------------------------------------
// K0: zero output + g_s, and pre-round [Wk; Wv] to tf32 into g_Wt
// ---------------------------------------------------------------------------
__global__ void k0_zero(float* __restrict__ out, int n,
                        const float* __restrict__ Wk,
                        const float* __restrict__ Wv) {
    int i = blockIdx.x * 256 + threadIdx.x;
    if (i < n) out[i] = 0.0f;
    if (i < BB * 256) g_s[i] = 0.0f;
    if (i < 512 * 256) {
        int r = i >> 8, c = i & 255;
        g_Wt[i] = to_tf32(r < 256 ? Wk[r * 256 + c] : Wv[(r - 256) * 256 + c]);
    }
}

// ---------------------------------------------------------------------------
// K1: (K|V) = W @ x + bias; K-tiles: exp + rowsum fused into epilogue.
// 256 thr (8 warps: 4m x 2n, warp tile 32x64), CTA tile 128x128,
// contraction chunk 32 (8 chunks), 3-stage cp.async ring, occ 2.
// A = g_Wt (tf32 already) in [m][k] stride 36. B = x in [k][n] stride 136
// (raw f32; cvt.rna applied on the fragment). grid (4 m-tiles, 128 n, 8 b).
// ---------------------------------------------------------------------------
#define SA1        36
#define SB1        136
#define K1_A_B     (128 * SA1 * 4)               // 18432
#define K1_B_B     (32 * SB1 * 4)                // 17408
#define K1_STG_B   (K1_A_B + K1_B_B)             // 35840 bytes/stage
#define K1_STG_F   (K1_STG_B / 4)
#define K1_SMEM    (3 * K1_STG_B)                // 107520

__device__ __forceinline__ void k1_prefetch(uint32_t smbase, int st,
                                            const float* Wt0, const float* Xb,
                                            int c0, int tid) {
    const uint32_t sA = smbase + (uint32_t)(st * K1_STG_B);
    const uint32_t sB = sA + K1_A_B;
    #pragma unroll
    for (int p = 0; p < 4; ++p) {            // A: 128 rows x 32 c
        const int idx = tid + p * 256;
        const int row = idx >> 3, q = (idx & 7) * 4;
        CPA16(sA + (uint32_t)(row * SA1 + q) * 4,
              Wt0 + (size_t)row * 256 + c0 + q);
    }
    #pragma unroll
    for (int p = 0; p < 4; ++p) {            // B: 32 k-rows x 128 n
        const int idx = tid + p * 256;
        const int k = idx >> 5, n4 = (idx & 31) * 4;
        CPA16(sB + (uint32_t)(k * SB1 + n4) * 4,
              Xb + (size_t)(c0 + k) * NN + n4);
    }
}

__global__ void __launch_bounds__(256, 2)
k1_gemm(const float* __restrict__ x,
        const float* __restrict__ bk, const float* __restrict__ bv) {
    extern __shared__ float sm1[];
    const uint32_t smbase = (uint32_t)__cvta_generic_to_shared(sm1);

    const int tid  = threadIdx.x;
    const int wid  = tid >> 5;
    const int lane = tid & 31;
    const int lr   = lane >> 2, lc = lane & 3;
    const int wm   = (wid & 3) * 32;
    const int wn   = (wid >> 2) * 64;

    const int mtile = blockIdx.x;            // 0..3
    const int n0    = blockIdx.y * 128;
    const int b     = blockIdx.z;
    const bool isK  = (mtile < 2);
    const int mrow0 = (mtile & 1) * 128;

    const float* Wt0 = g_Wt + (size_t)(mtile * 128) * 256;
    const float* Xb  = x + (size_t)b * CC * NN + n0;

    float acc[2][8][4];
    #pragma unroll
    for (int i = 0; i < 2; ++i)
        #pragma unroll
        for (int j = 0; j < 8; ++j)
            #pragma unroll
            for (int t = 0; t < 4; ++t) acc[i][j][t] = 0.0f;

    k1_prefetch(smbase, 0, Wt0, Xb, 0, tid);
    CPA_COMMIT();
    k1_prefetch(smbase, 1, Wt0, Xb, 32, tid);
    CPA_COMMIT();

    #pragma unroll
    for (int ic = 0; ic < 8; ++ic) {
        CPA_WAIT1();
        __syncthreads();
        const float* sA = sm1 + (ic % 3) * K1_STG_F;
        const float* sB = sA + K1_A_B / 4;

        #pragma unroll
        for (int ks = 0; ks < 4; ++ks) {
            const int kc = ks * 8;
            uint32_t a[2][4], bf[8][2];
            #pragma unroll
            for (int i = 0; i < 2; ++i) {
                const float* p0 = &sA[(wm + i * 16 + lr) * SA1 + kc + lc];
                const float* p1 = p0 + 8 * SA1;
                a[i][0] = __float_as_uint(p0[0]);
                a[i][1] = __float_as_uint(p1[0]);
                a[i][2] = __float_as_uint(p0[4]);
                a[i][3] = __float_as_uint(p1[4]);
            }
            #pragma unroll
            for (int j = 0; j < 8; ++j) {
                const float* q0 = &sB[(kc + lc) * SB1 + wn + j * 8 + lr];
                bf[j][0] = tf32_bits(q0[0]);
                bf[j][1] = tf32_bits(q0[4 * SB1]);
            }
            #pragma unroll
            for (int i = 0; i < 2; ++i)
                #pragma unroll
                for (int j = 0; j < 8; ++j) mma_tf32(acc[i][j], a[i], bf[j]);
        }

        if (ic + 2 < 8)
            k1_prefetch(smbase, (ic + 2) % 3, Wt0, Xb, (ic + 2) * 32, tid);
        CPA_COMMIT();
    }

    // Epilogue: bias, (exp + rowsum for K), tf32-round, store.
    const float* bias = isK ? bk : bv;
    float* gout = isK ? g_K : g_V;
    float rs[2][2] = {{0.f, 0.f}, {0.f, 0.f}};
    #pragma unroll
    for (int i = 0; i < 2; ++i) {
        const int ch0 = mrow0 + wm + i * 16 + lr;
        const int ch1 = ch0 + 8;
        const float b0 = bias[ch0], b1 = bias[ch1];
        float* r0 = gout + ((size_t)b * 256 + ch0) * NN + n0 + wn + 2 * lc;
        float* r1 = gout + ((size_t)b * 256 + ch1) * NN + n0 + wn + 2 * lc;
        #pragma unroll
        for (int j = 0; j < 8; ++j) {
            float v0 = acc[i][j][0] + b0, v1 = acc[i][j][1] + b0;
            float v2 = acc[i][j][2] + b1, v3 = acc[i][j][3] + b1;
            if (isK) {
                v0 = to_tf32(__expf(v0)); v1 = to_tf32(__expf(v1));
                v2 = to_tf32(__expf(v2)); v3 = to_tf32(__expf(v3));
                rs[i][0] += v0 + v1;
                rs[i][1] += v2 + v3;
            } else {
                v0 = to_tf32(v0); v1 = to_tf32(v1);
                v2 = to_tf32(v2); v3 = to_tf32(v3);
            }
            *(float2*)(r0 + j * 8) = make_float2(v0, v1);
            *(float2*)(r1 + j * 8) = make_float2(v2, v3);
        }
    }
    if (isK) {
        #pragma unroll
        for (int i = 0; i < 2; ++i)
            #pragma unroll
            for (int h = 0; h < 2; ++h) {
                float v = rs[i][h];
                v += __shfl_xor_sync(0xffffffffu, v, 1);
                v += __shfl_xor_sync(0xffffffffu, v, 2);
                if (lc == 0) {
                    int ch = mrow0 + wm + i * 16 + lr + h * 8;
                    atomicAdd(&g_s[b * 256 + ch], v);
                }
            }
    }
}

// ---------------------------------------------------------------------------
// K3: context = (1/s) * expK @ V^T. Inputs pre-rounded tf32 -> cp.async
// double-buffered loads, no cvt. 512 thr, warp tile 32x32, chunk 32,
// contraction split 8 ways (2048 each = 64 chunks). atomicAdd epilogue.
// ---------------------------------------------------------------------------
#define SMS3      36
#define K3_STAGE  (128 * SMS3 * 2)          // floats
#define K3_SMEM   (2 * K3_STAGE * 4)        // bytes

__device__ __forceinline__ void k3_prefetch(uint32_t smbase, int st,
                                            const float* Kb, const float* Vb,
                                            int c0, int tid) {
    const uint32_t sA = smbase + (uint32_t)(st * K3_STAGE * 4);
    const uint32_t sB = sA + 128 * SMS3 * 4;
    #pragma unroll
    for (int r = 0; r < 2; ++r) {
        const int idx2 = tid + r * 512;
        const int row = idx2 >> 3, q = (idx2 & 7) * 4;
        const uint32_t off = (uint32_t)(row * SMS3 + q) * 4;
        CPA16(sA + off, Kb + (size_t)row * NN + c0 + q);
        CPA16(sB + off, Vb + (size_t)row * NN + c0 + q);
    }
}

__global__ void __launch_bounds__(512, 1)
k3_context(float* __restrict__ out) {
    extern __shared__ float sm3[];
    const int tid  = threadIdx.x;
    const int wid  = tid >> 5;
    const int lane = tid & 31;
    const int lr   = lane >> 2, lc = lane & 3;
    const int wm   = (wid & 3) * 32;
    const int wn   = (wid >> 2) * 32;

    const int km0 = (blockIdx.x & 1) * 128;
    const int vm0 = (blockIdx.x >> 1) * 128;
    const int nb  = blockIdx.y * 2048;
    const int b   = blockIdx.z;

    const float* Kbase = g_K + ((size_t)b * 256 + km0) * NN + nb;
    const float* Vbase = g_V + ((size_t)b * 256 + vm0) * NN + nb;
    const uint32_t smbase = (uint32_t)__cvta_generic_to_shared(sm3);

    float acc[2][4][4];
    #pragma unroll
    for (int i = 0; i < 2; ++i)
        #pragma unroll
        for (int j = 0; j < 4; ++j)
            #pragma unroll
            for (int t = 0; t < 4; ++t) acc[i][j][t] = 0.0f;

    k3_prefetch(smbase, 0, Kbase, Vbase, 0, tid);
    CPA_COMMIT();
    k3_prefetch(smbase, 1, Kbase, Vbase, 32, tid);
    CPA_COMMIT();

    for (int ic = 0; ic < 64; ++ic) {
        CPA_WAIT1();
        __syncthreads();
        const float* sA = sm3 + (ic & 1) * K3_STAGE;
        const float* sB = sA + 128 * SMS3;

        #pragma unroll
        for (int ks = 0; ks < 4; ++ks) {
            const int kc = ks * 8;
            uint32_t a[2][4], bf[4][2];
            #pragma unroll
            for (int i = 0; i < 2; ++i) {
                const float* p0 = &sA[(wm + i * 16 + lr) * SMS3 + kc + lc];
                const float* p1 = p0 + 8 * SMS3;
                a[i][0] = __float_as_uint(p0[0]);
                a[i][1] = __float_as_uint(p1[0]);
                a[i][2] = __float_as_uint(p0[4]);
                a[i][3] = __float_as_uint(p1[4]);
            }
            #pragma unroll
            for (int j = 0; j < 4; ++j) {
                const float* p = &sB[(wn + j * 8 + lr) * SMS3 + kc + lc];
                bf[j][0] = __float_as_uint(p[0]);
                bf[j][1] = __float_as_uint(p[4]);
            }
            #pragma unroll
            for (int i = 0; i < 2; ++i)
                #pragma unroll
                for (int j = 0; j < 4; ++j) mma_tf32(acc[i][j], a[i], bf[j]);
        }
        __syncthreads();
        if (ic + 2 < 64)
            k3_prefetch(smbase, ic & 1, Kbase, Vbase, (ic + 2) * 32, tid);
        CPA_COMMIT();
    }

    #pragma unroll
    for (int i = 0; i < 2; ++i) {
        const int k0r = km0 + wm + i * 16 + lr;
        const int k1r = k0r + 8;
        const float inv0 = 1.0f / g_s[b * 256 + k0r];
        const float inv1 = 1.0f / g_s[b * 256 + k1r];
        float* r0 = out + ((size_t)b * 256 + k0r) * 256 + vm0 + wn + 2 * lc;
        float* r1 = out + ((size_t)b * 256 + k1r) * 256 + vm0 + wn + 2 * lc;
        #pragma unroll
        for (int j = 0; j < 4; ++j) {
            atomicAdd(r0 + j * 8,     acc[i][j][0] * inv0);
            atomicAdd(r0 + j * 8 + 1, acc[i][j][1] * inv0);
            atomicAdd(r1 + j * 8,     acc[i][j][2] * inv1);
            atomicAdd(r1 + j * 8 + 1, acc[i][j][3] * inv1);
        }
    }
}

// ---------------------------------------------------------------------------
// Launch
// ---------------------------------------------------------------------------
extern "C" void kernel_launch(void* const* d_in, const int* in_sizes, int n_in,
                              void* d_out, int out_size) {
    const float* x  = (const float*)d_in[0];
    const float* Wk = (const float*)d_in[1];
    const float* bk = (const float*)d_in[2];
    const float* Wv = (const float*)d_in[3];
    const float* bv = (const float*)d_in[4];
    float* out = (float*)d_out;

    cudaFuncSetAttribute(k1_gemm, cudaFuncAttributeMaxDynamicSharedMemorySize,
                         K1_SMEM);
    cudaFuncSetAttribute(k3_context, cudaFuncAttributeMaxDynamicSharedMemorySize,
                         K3_SMEM);

    k0_zero<<<(out_size + 255) / 256, 256>>>(out, out_size, Wk, Wv);

    dim3 g1(4, 128, BB);
    k1_gemm<<<g1, 256, K1_SMEM>>>(x, bk, bv);

    dim3 g3(4, 8, BB);
    k3_context<<<g3, 512, K3_SMEM>>>(out);
}

// round 7
// speedup vs baseline: 1.9064x; 1.5279x over previous
#include <cuda_runtime.h>
#include <cuda_fp16.h>
#include <cstdint>

#define BB   8
#define CC   256
#define NN   16384

// Scratch (device-global; no allocations allowed)
__device__ __half  g_Kh[(size_t)BB * 256 * NN];  // exp(K + bk), fp16 (64 MB)
__device__ __half  g_Vh[(size_t)BB * 256 * NN];  // V + bv, fp16 (64 MB)
__device__ float    g_s[BB * 256];               // softmax denominators
__device__ uint32_t g_Wh[512 * 128];             // [Wk; Wv] packed half2

// ---------------------------------------------------------------------------
// fp16 mma.sync m16n8k16 (fp32 accumulate) — 2x the tf32 HMMA rate.
// ---------------------------------------------------------------------------
__device__ __forceinline__ void mma_f16(float* d, const uint32_t* a,
                                        const uint32_t* b) {
    asm volatile(
        "mma.sync.aligned.m16n8k16.row.col.f32.f16.f16.f32 "
        "{%0,%1,%2,%3}, {%4,%5,%6,%7}, {%8,%9}, {%0,%1,%2,%3};"
        : "+f"(d[0]), "+f"(d[1]), "+f"(d[2]), "+f"(d[3])
        : "r"(a[0]), "r"(a[1]), "r"(a[2]), "r"(a[3]), "r"(b[0]), "r"(b[1]));
}

__device__ __forceinline__ uint32_t pack_h2(float lo, float hi) {
    __half2 h = __floats2half2_rn(lo, hi);
    return *(uint32_t*)&h;
}

#define CPA16(dst, src) \
    asm volatile("cp.async.cg.shared.global [%0], [%1], 16;" \
                 :: "r"(dst), "l"(src) : "memory")
#define CPA_COMMIT() asm volatile("cp.async.commit_group;" ::: "memory")
#define CPA_WAIT1()  asm volatile("cp.async.wait_group 1;" ::: "memory")

// ---------------------------------------------------------------------------
// K0: zero out + g_s; pack [Wk; Wv] into half2 pairs g_Wh
// ---------------------------------------------------------------------------
__global__ void k0_prep(float* __restrict__ out, int n,
                        const float* __restrict__ Wk,
                        const float* __restrict__ Wv) {
    int i = blockIdx.x * 256 + threadIdx.x;
    if (i < n) out[i] = 0.0f;
    if (i < BB * 256) g_s[i] = 0.0f;
    if (i < 512 * 128) {
        int r = i >> 7, c = (i & 127) * 2;
        const float* W = (r < 256) ? &Wk[r * 256 + c] : &Wv[(r - 256) * 256 + c];
        g_Wh[i] = pack_h2(W[0], W[1]);
    }
}

// ---------------------------------------------------------------------------
// K1: (K|V) = W @ x + bias; K: exp + rowsum fused. fp16 MMA.
// 256 thr (8 warps: 4m x 2n, warp tile 32x64), CTA tile 128x128,
// chunk 32 channels, 3-stage cp.async ring.
// A = g_Wh half2 [m][16 u32] stride 20. B = x f32 [k][128 n] stride 132
// (cvt.rn.f16x2 on the fragment). grid (4 m-tiles, 128 n, 8 b).
// ---------------------------------------------------------------------------
#define SA1U      20
#define SB1F      132
#define K1_A_B    (128 * SA1U * 4)               // 10240
#define K1_B_B    (32 * SB1F * 4)                // 16896
#define K1_STG    (K1_A_B + K1_B_B)              // 27136 bytes/stage
#define K1_SMEM   (3 * K1_STG)                   // 81408

__device__ __forceinline__ void k1_prefetch(uint32_t smbase, int st,
                                            const uint32_t* Wh0,
                                            const float* Xb, int c0, int tid) {
    const uint32_t sA = smbase + (uint32_t)(st * K1_STG);
    const uint32_t sB = sA + K1_A_B;
    const int c0h = c0 >> 1;                 // pair index base
    #pragma unroll
    for (int p = 0; p < 2; ++p) {            // A: 128 rows x 16 u32
        const int idx = tid + p * 256;
        const int row = idx >> 2, qu = (idx & 3) * 4;
        CPA16(sA + (uint32_t)(row * SA1U + qu) * 4,
              Wh0 + (size_t)row * 128 + c0h + qu);
    }
    #pragma unroll
    for (int p = 0; p < 4; ++p) {            // B: 32 k-rows x 128 n f32
        const int idx = tid + p * 256;
        const int k = idx >> 5, n4 = (idx & 31) * 4;
        CPA16(sB + (uint32_t)(k * SB1F + n4) * 4,
              Xb + (size_t)(c0 + k) * NN + n4);
    }
}

__global__ void __launch_bounds__(256, 2)
k1_gemm(const float* __restrict__ x,
        const float* __restrict__ bk, const float* __restrict__ bv) {
    extern __shared__ char sm1[];
    const uint32_t smbase = (uint32_t)__cvta_generic_to_shared(sm1);

    const int tid  = threadIdx.x;
    const int wid  = tid >> 5;
    const int lane = tid & 31;
    const int lr   = lane >> 2, lc = lane & 3;
    const int wm   = (wid & 3) * 32;
    const int wn   = (wid >> 2) * 64;

    const int mtile = blockIdx.x;            // 0..3
    const int n0    = blockIdx.y * 128;
    const int b     = blockIdx.z;
    const bool isK  = (mtile < 2);
    const int mrow0 = (mtile & 1) * 128;

    const uint32_t* Wh0 = g_Wh + (size_t)(mtile * 128) * 128;
    const float* Xb = x + (size_t)b * CC * NN + n0;

    float acc[2][8][4];
    #pragma unroll
    for (int i = 0; i < 2; ++i)
        #pragma unroll
        for (int j = 0; j < 8; ++j)
            #pragma unroll
            for (int t = 0; t < 4; ++t) acc[i][j][t] = 0.0f;

    k1_prefetch(smbase, 0, Wh0, Xb, 0, tid);
    CPA_COMMIT();
    k1_prefetch(smbase, 1, Wh0, Xb, 32, tid);
    CPA_COMMIT();

    #pragma unroll
    for (int ic = 0; ic < 8; ++ic) {
        CPA_WAIT1();
        __syncthreads();
        const uint32_t* sAu = (const uint32_t*)(sm1 + (ic % 3) * K1_STG);
        const float*    sBf = (const float*)(sm1 + (ic % 3) * K1_STG + K1_A_B);

        #pragma unroll
        for (int ks = 0; ks < 2; ++ks) {     // two k16 steps per chunk32
            uint32_t a[2][4], bf[8][2];
            #pragma unroll
            for (int i = 0; i < 2; ++i) {
                const int base = (wm + i * 16 + lr) * SA1U + ks * 8 + lc;
                a[i][0] = sAu[base];
                a[i][1] = sAu[base + 8 * SA1U];
                a[i][2] = sAu[base + 4];
                a[i][3] = sAu[base + 8 * SA1U + 4];
            }
            #pragma unroll
            for (int j = 0; j < 8; ++j) {
                const int n = wn + j * 8 + lr;
                const float* p = &sBf[(ks * 16 + 2 * lc) * SB1F + n];
                bf[j][0] = pack_h2(p[0], p[SB1F]);
                bf[j][1] = pack_h2(p[8 * SB1F], p[9 * SB1F]);
            }
            #pragma unroll
            for (int i = 0; i < 2; ++i)
                #pragma unroll
                for (int j = 0; j < 8; ++j) mma_f16(acc[i][j], a[i], bf[j]);
        }

        if (ic + 2 < 8)
            k1_prefetch(smbase, (ic + 2) % 3, Wh0, Xb, (ic + 2) * 32, tid);
        CPA_COMMIT();
    }

    // Epilogue: bias, (exp + rowsum for K), fp16-round, store half2.
    const float* bias = isK ? bk : bv;
    __half* gout = isK ? g_Kh : g_Vh;
    float rs[2][2] = {{0.f, 0.f}, {0.f, 0.f}};
    #pragma unroll
    for (int i = 0; i < 2; ++i) {
        const int ch0 = mrow0 + wm + i * 16 + lr;
        const int ch1 = ch0 + 8;
        const float b0 = bias[ch0], b1 = bias[ch1];
        uint32_t* r0 = (uint32_t*)(gout + ((size_t)b * 256 + ch0) * NN + n0 + wn + 2 * lc);
        uint32_t* r1 = (uint32_t*)(gout + ((size_t)b * 256 + ch1) * NN + n0 + wn + 2 * lc);
        #pragma unroll
        for (int j = 0; j < 8; ++j) {
            float v0 = acc[i][j][0] + b0, v1 = acc[i][j][1] + b0;
            float v2 = acc[i][j][2] + b1, v3 = acc[i][j][3] + b1;
            if (isK) {
                v0 = __expf(v0); v1 = __expf(v1);
                v2 = __expf(v2); v3 = __expf(v3);
            }
            __half2 h0 = __floats2half2_rn(v0, v1);
            __half2 h1 = __floats2half2_rn(v2, v3);
            if (isK) {           // rowsum of the ROUNDED values (cancels in softmax)
                float2 f0 = __half22float2(h0);
                float2 f1 = __half22float2(h1);
                rs[i][0] += f0.x + f0.y;
                rs[i][1] += f1.x + f1.y;
            }
            r0[j * 4] = *(uint32_t*)&h0;     // j*8 halves = j*4 u32
            r1[j * 4] = *(uint32_t*)&h1;
        }
    }
    if (isK) {
        #pragma unroll
        for (int i = 0; i < 2; ++i)
            #pragma unroll
            for (int h = 0; h < 2; ++h) {
                float v = rs[i][h];
                v += __shfl_xor_sync(0xffffffffu, v, 1);
                v += __shfl_xor_sync(0xffffffffu, v, 2);
                if (lc == 0) {
                    int ch = mrow0 + wm + i * 16 + lr + h * 8;
                    atomicAdd(&g_s[b * 256 + ch], v);
                }
            }
    }
}

// ---------------------------------------------------------------------------
// K3: context = (1/s) * expK @ V^T, all fp16 operands (pre-rounded), f32 acc.
// 256 thr, warp tile 32x64, CTA 128x128, chunk 32 spatial, 3-stage ring,
// contraction split 8 ways (2048 each = 64 chunks). atomicAdd epilogue.
// grid (4 output tiles, 8 splits, 8 b).
// ---------------------------------------------------------------------------
#define SA3U      20
#define K3_T_B    (128 * SA3U * 4)              // 10240 per tile
#define K3_STG    (2 * K3_T_B)                  // 20480 bytes/stage
#define K3_SMEM   (3 * K3_STG)                  // 61440

__device__ __forceinline__ void k3_prefetch(uint32_t smbase, int st,
                                            const __half* Kb, const __half* Vb,
                                            int c0, int tid) {
    const uint32_t sA = smbase + (uint32_t)(st * K3_STG);
    const uint32_t sB = sA + K3_T_B;
    #pragma unroll
    for (int p = 0; p < 2; ++p) {
        const int idx = tid + p * 256;
        const int row = idx >> 2, qu = (idx & 3) * 4;   // 4 u32 = 8 halves
        const uint32_t off = (uint32_t)(row * SA3U + qu) * 4;
        CPA16(sA + off, Kb + (size_t)row * NN + c0 + qu * 2);
        CPA16(sB + off, Vb + (size_t)row * NN + c0 + qu * 2);
    }
}

__global__ void __launch_bounds__(256, 2)
k3_context(float* __restrict__ out) {
    extern __shared__ char sm3[];
    const uint32_t smbase = (uint32_t)__cvta_generic_to_shared(sm3);

    const int tid  = threadIdx.x;
    const int wid  = tid >> 5;
    const int lane = tid & 31;
    const int lr   = lane >> 2, lc = lane & 3;
    const int wm   = (wid & 3) * 32;
    const int wn   = (wid >> 2) * 64;

    const int km0 = (blockIdx.x & 1) * 128;
    const int vm0 = (blockIdx.x >> 1) * 128;
    const int nb  = blockIdx.y * 2048;
    const int b   = blockIdx.z;

    const __half* Kb = g_Kh + ((size_t)b * 256 + km0) * NN + nb;
    const __half* Vb = g_Vh + ((size_t)b * 256 + vm0) * NN + nb;

    float acc[2][8][4];
    #pragma unroll
    for (int i = 0; i < 2; ++i)
        #pragma unroll
        for (int j = 0; j < 8; ++j)
            #pragma unroll
            for (int t = 0; t < 4; ++t) acc[i][j][t] = 0.0f;

    k3_prefetch(smbase, 0, Kb, Vb, 0, tid);
    CPA_COMMIT();
    k3_prefetch(smbase, 1, Kb, Vb, 32, tid);
    CPA_COMMIT();

    for (int ic = 0; ic < 64; ++ic) {
        CPA_WAIT1();
        __syncthreads();
        const uint32_t* sAu = (const uint32_t*)(sm3 + (ic % 3) * K3_STG);
        const uint32_t* sBu = (const uint32_t*)(sm3 + (ic % 3) * K3_STG + K3_T_B);

        #pragma unroll
        for (int ks = 0; ks < 2; ++ks) {
            uint32_t a[2][4], bf[8][2];
            #pragma unroll
            for (int i = 0; i < 2; ++i) {
                const int base = (wm + i * 16 + lr) * SA3U + ks * 8 + lc;
                a[i][0] = sAu[base];
                a[i][1] = sAu[base + 8 * SA3U];
                a[i][2] = sAu[base + 4];
                a[i][3] = sAu[base + 8 * SA3U + 4];
            }
            #pragma unroll
            for (int j = 0; j < 8; ++j) {
                const int base = (wn + j * 8 + lr) * SA3U + ks * 8 + lc;
                bf[j][0] = sBu[base];
                bf[j][1] = sBu[base + 4];
            }
            #pragma unroll
            for (int i = 0; i < 2; ++i)
                #pragma unroll
                for (int j = 0; j < 8; ++j) mma_f16(acc[i][j], a[i], bf[j]);
        }

        if (ic + 2 < 64)
            k3_prefetch(smbase, (ic + 2) % 3, Kb, Vb, (ic + 2) * 32, tid);
        CPA_COMMIT();
    }

    #pragma unroll
    for (int i = 0; i < 2; ++i) {
        const int k0r = km0 + wm + i * 16 + lr;
        const int k1r = k0r + 8;
        const float inv0 = 1.0f / g_s[b * 256 + k0r];
        const float inv1 = 1.0f / g_s[b * 256 + k1r];
        float* r0 = out + ((size_t)b * 256 + k0r) * 256 + vm0 + wn + 2 * lc;
        float* r1 = out + ((size_t)b * 256 + k1r) * 256 + vm0 + wn + 2 * lc;
        #pragma unroll
        for (int j = 0; j < 8; ++j) {
            atomicAdd(r0 + j * 8,     acc[i][j][0] * inv0);
            atomicAdd(r0 + j * 8 + 1, acc[i][j][1] * inv0);
            atomicAdd(r1 + j * 8,     acc[i][j][2] * inv1);
            atomicAdd(r1 + j * 8 + 1, acc[i][j][3] * inv1);
        }
    }
}

// ---------------------------------------------------------------------------
// Launch
// ---------------------------------------------------------------------------
extern "C" void kernel_launch(void* const* d_in, const int* in_sizes, int n_in,
                              void* d_out, int out_size) {
    const float* x  = (const float*)d_in[0];
    const float* Wk = (const float*)d_in[1];
    const float* bk = (const float*)d_in[2];
    const float* Wv = (const float*)d_in[3];
    const float* bv = (const float*)d_in[4];
    float* out = (float*)d_out;

    cudaFuncSetAttribute(k1_gemm, cudaFuncAttributeMaxDynamicSharedMemorySize,
                         K1_SMEM);
    cudaFuncSetAttribute(k3_context, cudaFuncAttributeMaxDynamicSharedMemorySize,
                         K3_SMEM);

    k0_prep<<<(out_size + 255) / 256, 256>>>(out, out_size, Wk, Wv);

    dim3 g1(4, 128, BB);
    k1_gemm<<<g1, 256, K1_SMEM>>>(x, bk, bv);

    dim3 g3(4, 8, BB);
    k3_context<<<g3, 256, K3_SMEM>>>(out);
}

// round 8
// speedup vs baseline: 1.9679x; 1.0322x over previous
#include <cuda_runtime.h>
#include <cuda_fp16.h>
#include <cstdint>

#define BB   8
#define CC   256
#define NN   16384

// Scratch (device-global; no allocations allowed)
__device__ __half  g_Kh[(size_t)BB * 256 * NN];  // exp(K + bk), fp16 (64 MB)
__device__ __half  g_Vh[(size_t)BB * 256 * NN];  // V + bv, fp16 (64 MB)
__device__ float    g_s[BB * 256];               // softmax denominators
__device__ uint32_t g_Wh[512 * 128];             // [Wk; Wv] packed half2

// ---------------------------------------------------------------------------
// fp16 mma.sync m16n8k16 (fp32 accumulate)
// ---------------------------------------------------------------------------
__device__ __forceinline__ void mma_f16(float* d, const uint32_t* a,
                                        const uint32_t* b) {
    asm volatile(
        "mma.sync.aligned.m16n8k16.row.col.f32.f16.f16.f32 "
        "{%0,%1,%2,%3}, {%4,%5,%6,%7}, {%8,%9}, {%0,%1,%2,%3};"
        : "+f"(d[0]), "+f"(d[1]), "+f"(d[2]), "+f"(d[3])
        : "r"(a[0]), "r"(a[1]), "r"(a[2]), "r"(a[3]), "r"(b[0]), "r"(b[1]));
}

__device__ __forceinline__ uint32_t pack_h2(float lo, float hi) {
    __half2 h = __floats2half2_rn(lo, hi);
    return *(uint32_t*)&h;
}

#define CPA16(dst, src) \
    asm volatile("cp.async.cg.shared.global [%0], [%1], 16;" \
                 :: "r"(dst), "l"(src) : "memory")
#define CPA_COMMIT() asm volatile("cp.async.commit_group;" ::: "memory")
#define CPA_WAIT1()  asm volatile("cp.async.wait_group 1;" ::: "memory")
#define CPA_WAIT0()  asm volatile("cp.async.wait_group 0;" ::: "memory")

// ---------------------------------------------------------------------------
// K0: zero out + g_s; pack [Wk; Wv] into half2 pairs g_Wh
// ---------------------------------------------------------------------------
__global__ void k0_prep(float* __restrict__ out, int n,
                        const float* __restrict__ Wk,
                        const float* __restrict__ Wv) {
    int i = blockIdx.x * 256 + threadIdx.x;
    if (i < n) out[i] = 0.0f;
    if (i < BB * 256) g_s[i] = 0.0f;
    if (i < 512 * 128) {
        int r = i >> 7, c = (i & 127) * 2;
        const float* W = (r < 256) ? &Wk[r * 256 + c] : &Wv[(r - 256) * 256 + c];
        g_Wh[i] = pack_h2(W[0], W[1]);
    }
}

// ---------------------------------------------------------------------------
// K1: (K|V) = W @ x + bias; K: exp + rowsum fused. fp16 MMA.
// 256 thr (8 warps: 4m x 2n), CTA tile 128x128, chunk 32 channels.
// A: FULL W tile (128 m x 256 k fp16) loaded once via cp.async, stride 132 u32
//    (4*lr+lc bank-exact). B: x gathered LDG f32 -> cvt f16x2 -> STS.64,
//    [n][k] fp16 stride 20 u32, register-double-buffered, 1 sync/chunk.
// grid (4 m-tiles, 128 n-tiles, 8 b), occ 2.
// ---------------------------------------------------------------------------
#define ASTR      132                            // u32 per A row
#define K1_A_B    (128 * ASTR * 4)               // 67584
#define SBU       20                             // u32 per B row
#define K1_B_B    (128 * SBU * 4)                // 10240 per buffer
#define K1_SMEM   (K1_A_B + 2 * K1_B_B)          // 88064

__global__ void __launch_bounds__(256, 2)
k1_gemm(const float* __restrict__ x,
        const float* __restrict__ bk, const float* __restrict__ bv) {
    extern __shared__ char sm1[];
    const uint32_t smbase = (uint32_t)__cvta_generic_to_shared(sm1);

    const int tid  = threadIdx.x;
    const int wid  = tid >> 5;
    const int lane = tid & 31;
    const int lr   = lane >> 2, lc = lane & 3;
    const int wm   = (wid & 3) * 32;
    const int wn   = (wid >> 2) * 64;

    const int mtile = blockIdx.x;            // 0..3
    const int n0    = blockIdx.y * 128;
    const int b     = blockIdx.z;
    const bool isK  = (mtile < 2);
    const int mrow0 = (mtile & 1) * 128;

    const uint32_t* Wh0 = g_Wh + (size_t)(mtile * 128) * 128;
    const float* Xb = x + (size_t)b * CC * NN + n0;

    // ---- issue full-A cp.async (128 rows x 128 u32) ----
    #pragma unroll
    for (int p = 0; p < 16; ++p) {
        const int idx = tid + p * 256;
        const int row = idx >> 5, qu = (idx & 31) * 4;
        CPA16(smbase + (uint32_t)(row * ASTR + qu) * 4,
              Wh0 + (size_t)row * 128 + qu);
    }
    CPA_COMMIT();

    const uint32_t* sAu = (const uint32_t*)sm1;
    uint32_t* sB[2] = {(uint32_t*)(sm1 + K1_A_B),
                       (uint32_t*)(sm1 + K1_A_B + K1_B_B)};

    float acc[2][8][4];
    #pragma unroll
    for (int i = 0; i < 2; ++i)
        #pragma unroll
        for (int j = 0; j < 8; ++j)
            #pragma unroll
            for (int t = 0; t < 4; ++t) acc[i][j][t] = 0.0f;

    // B gather state: warp wid owns channels c0+4wid..+3, lanes = n
    float bT[4][4];                          // [i2][channel]
    const float* Xw = Xb + (size_t)(4 * wid) * NN;

    // ldg chunk 0
    #pragma unroll
    for (int i2 = 0; i2 < 4; ++i2) {
        const int nl = i2 * 32 + lane;
        bT[i2][0] = Xw[nl];
        bT[i2][1] = Xw[(size_t)NN + nl];
        bT[i2][2] = Xw[2 * (size_t)NN + nl];
        bT[i2][3] = Xw[3 * (size_t)NN + nl];
    }
    CPA_WAIT0();                             // A resident
    // sts chunk 0 -> buf 0
    #pragma unroll
    for (int i2 = 0; i2 < 4; ++i2) {
        const int nl = i2 * 32 + lane;
        uint32_t* d = sB[0] + nl * SBU + 2 * wid;
        d[0] = pack_h2(bT[i2][0], bT[i2][1]);
        d[1] = pack_h2(bT[i2][2], bT[i2][3]);
    }
    __syncthreads();

    #pragma unroll
    for (int ic = 0; ic < 8; ++ic) {
        if (ic < 7) {                        // ldg chunk ic+1
            const float* Xc = Xw + (size_t)(ic + 1) * 32 * NN;
            #pragma unroll
            for (int i2 = 0; i2 < 4; ++i2) {
                const int nl = i2 * 32 + lane;
                bT[i2][0] = Xc[nl];
                bT[i2][1] = Xc[(size_t)NN + nl];
                bT[i2][2] = Xc[2 * (size_t)NN + nl];
                bT[i2][3] = Xc[3 * (size_t)NN + nl];
            }
        }

        const uint32_t* sBu = sB[ic & 1];
        const int abase = ic * 16;           // u32 col offset into A
        #pragma unroll
        for (int ks = 0; ks < 2; ++ks) {
            uint32_t a[2][4], bf[8][2];
            #pragma unroll
            for (int i = 0; i < 2; ++i) {
                const int base = (wm + i * 16 + lr) * ASTR + abase + ks * 8 + lc;
                a[i][0] = sAu[base];
                a[i][1] = sAu[base + 8 * ASTR];
                a[i][2] = sAu[base + 4];
                a[i][3] = sAu[base + 8 * ASTR + 4];
            }
            #pragma unroll
            for (int j = 0; j < 8; ++j) {
                const int base = (wn + j * 8 + lr) * SBU + ks * 8 + lc;
                bf[j][0] = sBu[base];
                bf[j][1] = sBu[base + 4];
            }
            #pragma unroll
            for (int i = 0; i < 2; ++i)
                #pragma unroll
                for (int j = 0; j < 8; ++j) mma_f16(acc[i][j], a[i], bf[j]);
        }

        if (ic < 7) {                        // sts chunk ic+1 -> other buf
            uint32_t* d0 = sB[(ic + 1) & 1];
            #pragma unroll
            for (int i2 = 0; i2 < 4; ++i2) {
                const int nl = i2 * 32 + lane;
                uint32_t* d = d0 + nl * SBU + 2 * wid;
                d[0] = pack_h2(bT[i2][0], bT[i2][1]);
                d[1] = pack_h2(bT[i2][2], bT[i2][3]);
            }
        }
        __syncthreads();
    }

    // Epilogue: bias, (exp + rowsum for K), fp16-round, store half2.
    const float* bias = isK ? bk : bv;
    __half* gout = isK ? g_Kh : g_Vh;
    float rs[2][2] = {{0.f, 0.f}, {0.f, 0.f}};
    #pragma unroll
    for (int i = 0; i < 2; ++i) {
        const int ch0 = mrow0 + wm + i * 16 + lr;
        const int ch1 = ch0 + 8;
        const float b0 = bias[ch0], b1 = bias[ch1];
        uint32_t* r0 = (uint32_t*)(gout + ((size_t)b * 256 + ch0) * NN + n0 + wn + 2 * lc);
        uint32_t* r1 = (uint32_t*)(gout + ((size_t)b * 256 + ch1) * NN + n0 + wn + 2 * lc);
        #pragma unroll
        for (int j = 0; j < 8; ++j) {
            float v0 = acc[i][j][0] + b0, v1 = acc[i][j][1] + b0;
            float v2 = acc[i][j][2] + b1, v3 = acc[i][j][3] + b1;
            if (isK) {
                v0 = __expf(v0); v1 = __expf(v1);
                v2 = __expf(v2); v3 = __expf(v3);
            }
            __half2 h0 = __floats2half2_rn(v0, v1);
            __half2 h1 = __floats2half2_rn(v2, v3);
            if (isK) {           // rowsum of ROUNDED values (cancels in softmax)
                float2 f0 = __half22float2(h0);
                float2 f1 = __half22float2(h1);
                rs[i][0] += f0.x + f0.y;
                rs[i][1] += f1.x + f1.y;
            }
            r0[j * 4] = *(uint32_t*)&h0;
            r1[j * 4] = *(uint32_t*)&h1;
        }
    }
    if (isK) {
        #pragma unroll
        for (int i = 0; i < 2; ++i)
            #pragma unroll
            for (int h = 0; h < 2; ++h) {
                float v = rs[i][h];
                v += __shfl_xor_sync(0xffffffffu, v, 1);
                v += __shfl_xor_sync(0xffffffffu, v, 2);
                if (lc == 0) {
                    int ch = mrow0 + wm + i * 16 + lr + h * 8;
                    atomicAdd(&g_s[b * 256 + ch], v);
                }
            }
    }
}

// ---------------------------------------------------------------------------
// K3: context = (1/s) * expK @ V^T, all fp16 operands, f32 acc.
// 256 thr, warp tile 32x64, CTA 128x128, chunk 32 spatial, 3-stage ring,
// contraction split 8 ways. grid (4 tiles, 8 splits, 8 b). (unchanged R7)
// ---------------------------------------------------------------------------
#define SA3U      20
#define K3_T_B    (128 * SA3U * 4)              // 10240 per tile
#define K3_STG    (2 * K3_T_B)                  // 20480 bytes/stage
#define K3_SMEM   (3 * K3_STG)                  // 61440

__device__ __forceinline__ void k3_prefetch(uint32_t smbase, int st,
                                            const __half* Kb, const __half* Vb,
                                            int c0, int tid) {
    const uint32_t sA = smbase + (uint32_t)(st * K3_STG);
    const uint32_t sB = sA + K3_T_B;
    #pragma unroll
    for (int p = 0; p < 2; ++p) {
        const int idx = tid + p * 256;
        const int row = idx >> 2, qu = (idx & 3) * 4;
        const uint32_t off = (uint32_t)(row * SA3U + qu) * 4;
        CPA16(sA + off, Kb + (size_t)row * NN + c0 + qu * 2);
        CPA16(sB + off, Vb + (size_t)row * NN + c0 + qu * 2);
    }
}

__global__ void __launch_bounds__(256, 2)
k3_context(float* __restrict__ out) {
    extern __shared__ char sm3[];
    const uint32_t smbase = (uint32_t)__cvta_generic_to_shared(sm3);

    const int tid  = threadIdx.x;
    const int wid  = tid >> 5;
    const int lane = tid & 31;
    const int lr   = lane >> 2, lc = lane & 3;
    const int wm   = (wid & 3) * 32;
    const int wn   = (wid >> 2) * 64;

    const int km0 = (blockIdx.x & 1) * 128;
    const int vm0 = (blockIdx.x >> 1) * 128;
    const int nb  = blockIdx.y * 2048;
    const int b   = blockIdx.z;

    const __half* Kb = g_Kh + ((size_t)b * 256 + km0) * NN + nb;
    const __half* Vb = g_Vh + ((size_t)b * 256 + vm0) * NN + nb;

    float acc[2][8][4];
    #pragma unroll
    for (int i = 0; i < 2; ++i)
        #pragma unroll
        for (int j = 0; j < 8; ++j)
            #pragma unroll
            for (int t = 0; t < 4; ++t) acc[i][j][t] = 0.0f;

    k3_prefetch(smbase, 0, Kb, Vb, 0, tid);
    CPA_COMMIT();
    k3_prefetch(smbase, 1, Kb, Vb, 32, tid);
    CPA_COMMIT();

    for (int ic = 0; ic < 64; ++ic) {
        CPA_WAIT1();
        __syncthreads();
        const uint32_t* sAu = (const uint32_t*)(sm3 + (ic % 3) * K3_STG);
        const uint32_t* sBu = (const uint32_t*)(sm3 + (ic % 3) * K3_STG + K3_T_B);

        #pragma unroll
        for (int ks = 0; ks < 2; ++ks) {
            uint32_t a[2][4], bf[8][2];
            #pragma unroll
            for (int i = 0; i < 2; ++i) {
                const int base = (wm + i * 16 + lr) * SA3U + ks * 8 + lc;
                a[i][0] = sAu[base];
                a[i][1] = sAu[base + 8 * SA3U];
                a[i][2] = sAu[base + 4];
                a[i][3] = sAu[base + 8 * SA3U + 4];
            }
            #pragma unroll
            for (int j = 0; j < 8; ++j) {
                const int base = (wn + j * 8 + lr) * SA3U + ks * 8 + lc;
                bf[j][0] = sBu[base];
                bf[j][1] = sBu[base + 4];
            }
            #pragma unroll
            for (int i = 0; i < 2; ++i)
                #pragma unroll
                for (int j = 0; j < 8; ++j) mma_f16(acc[i][j], a[i], bf[j]);
        }

        if (ic + 2 < 64)
            k3_prefetch(smbase, (ic + 2) % 3, Kb, Vb, (ic + 2) * 32, tid);
        CPA_COMMIT();
    }

    #pragma unroll
    for (int i = 0; i < 2; ++i) {
        const int k0r = km0 + wm + i * 16 + lr;
        const int k1r = k0r + 8;
        const float inv0 = 1.0f / g_s[b * 256 + k0r];
        const float inv1 = 1.0f / g_s[b * 256 + k1r];
        float* r0 = out + ((size_t)b * 256 + k0r) * 256 + vm0 + wn + 2 * lc;
        float* r1 = out + ((size_t)b * 256 + k1r) * 256 + vm0 + wn + 2 * lc;
        #pragma unroll
        for (int j = 0; j < 8; ++j) {
            atomicAdd(r0 + j * 8,     acc[i][j][0] * inv0);
            atomicAdd(r0 + j * 8 + 1, acc[i][j][1] * inv0);
            atomicAdd(r1 + j * 8,     acc[i][j][2] * inv1);
            atomicAdd(r1 + j * 8 + 1, acc[i][j][3] * inv1);
        }
    }
}

// ---------------------------------------------------------------------------
// Launch
// ---------------------------------------------------------------------------
extern "C" void kernel_launch(void* const* d_in, const int* in_sizes, int n_in,
                              void* d_out, int out_size) {
    const float* x  = (const float*)d_in[0];
    const float* Wk = (const float*)d_in[1];
    const float* bk = (const float*)d_in[2];
    const float* Wv = (const float*)d_in[3];
    const float* bv = (const float*)d_in[4];
    float* out = (float*)d_out;

    cudaFuncSetAttribute(k1_gemm, cudaFuncAttributeMaxDynamicSharedMemorySize,
                         K1_SMEM);
    cudaFuncSetAttribute(k3_context, cudaFuncAttributeMaxDynamicSharedMemorySize,
                         K3_SMEM);

    k0_prep<<<(out_size + 255) / 256, 256>>>(out, out_size, Wk, Wv);

    dim3 g1(4, 128, BB);
    k1_gemm<<<g1, 256, K1_SMEM>>>(x, bk, bv);

    dim3 g3(4, 8, BB);
    k3_context<<<g3, 256, K3_SMEM>>>(out);
}